// round 7
// baseline (speedup 1.0000x reference)
#include <cuda_runtime.h>
#include <math.h>

#define Bn 64
#define Tn 400
#define Hn 256
#define En 128
#define Vn 50000
#define Xn 500

#define OFF_FINAL 0
#define OFF_HS   (Bn*(Vn+Xn))
#define OFF_CS   (OFF_HS + Bn*Hn)
#define OFF_CT   (OFF_CS + Bn*Hn)
#define OFF_ATTN (OFF_CT + Bn*2*Hn)
#define OFF_PGEN (OFF_ATTN + Bn*Tn)
#define OFF_COV  (OFF_PGEN + Bn)

__device__ float g_x[Bn*En];
__device__ float g_dec[Bn*2*Hn];
__device__ float g_escore[Bn*Tn];   // exp(score)*mask
__device__ float g_outhid[Bn*Hn];
__device__ float g_elog[Bn*Vn];     // exp(logit + bias)
__device__ float g_rowsum[Bn];

__device__ __forceinline__ float warp_sum(float v){
    #pragma unroll
    for (int o = 16; o > 0; o >>= 1) v += __shfl_xor_sync(0xffffffffu, v, o);
    return v;
}
__device__ __forceinline__ float sigmoidf_(float x){ return 1.0f / (1.0f + expf(-x)); }
__device__ __forceinline__ float tanh_fast(float x){
    float r; asm("tanh.approx.f32 %0, %1;" : "=f"(r) : "f"(x)); return r;
}
__device__ __forceinline__ unsigned long long pack2(float x, float y){
    unsigned long long r; asm("mov.b64 %0, {%1,%2};" : "=l"(r) : "f"(x), "f"(y)); return r;
}
__device__ __forceinline__ void unpack2(unsigned long long a, float &x, float &y){
    asm("mov.b64 {%0,%1}, %2;" : "=f"(x), "=f"(y) : "l"(a));
}
__device__ __forceinline__ unsigned long long fma2_(unsigned long long a, unsigned long long b, unsigned long long c){
    unsigned long long d; asm("fma.rn.f32x2 %0, %1, %2, %3;" : "=l"(d) : "l"(a), "l"(b), "l"(c)); return d;
}

// ============ K1: fused x -> gates -> lstm -> dec_fea (2 batches / block) ============
__global__ void __launch_bounds__(1024) k_pre(const int* __restrict__ y_t_1,
        const float* __restrict__ c_t_1, const float* __restrict__ embedding,
        const float* __restrict__ Wxc, const float* __restrict__ bxc,
        const float* __restrict__ h0, const float* __restrict__ c0,
        const float* __restrict__ W_ih, const float* __restrict__ W_hh,
        const float* __restrict__ b_ih, const float* __restrict__ b_hh,
        const float* __restrict__ Wdp, const float* __restrict__ bdp,
        float* __restrict__ out){
    __shared__ float s_ct1[2][512], s_emb[2][128], s_x[2][128], s_h0[2][256];
    __shared__ float s_gates[2][1024], s_hs[2][256], s_cs[2][256];
    int tid = threadIdx.x;
    int lane = tid & 31, wid = tid >> 5;   // 32 warps
    int b0 = blockIdx.x * 2;

    // housekeeping: zero out[OFF_CT] region; zero row sums
    out[OFF_CT + blockIdx.x * 1024 + tid] = 0.0f;
    if (blockIdx.x == 0 && tid < Bn) g_rowsum[tid] = 0.0f;

    // stage A: stage activations into smem (disjoint assignments, no races)
    {
        int y0 = y_t_1[b0], y1 = y_t_1[b0+1];
        if (tid < 512){
            s_ct1[0][tid] = c_t_1[b0*512 + tid];
            s_ct1[1][tid] = c_t_1[(b0+1)*512 + tid];
        } else if (tid < 640){
            s_emb[0][tid-512] = embedding[(size_t)y0*En + (tid-512)];
        } else if (tid < 768){
            s_emb[1][tid-640] = embedding[(size_t)y1*En + (tid-640)];
        } else {
            int i = tid - 768;  // 256 threads
            s_h0[0][i] = h0[b0*Hn + i];
            s_h0[1][i] = h0[(b0+1)*Hn + i];
        }
    }
    __syncthreads();

    // stage B: x[j] = cat(c_t_1, emb) . Wxc_row(j) + bxc ; 128 j, 32 warps
    for (int j = wid; j < 128; j += 32){
        const float* wr = Wxc + j * 640;
        float a0 = 0.f, a1 = 0.f;
        #pragma unroll
        for (int it = 0; it < 16; it++){
            int k = lane + it*32;
            float wv = wr[k];
            a0 += s_ct1[0][k] * wv;
            a1 += s_ct1[1][k] * wv;
        }
        #pragma unroll
        for (int it = 0; it < 4; it++){
            int k = lane + it*32;
            float wv = wr[512 + k];
            a0 += s_emb[0][k] * wv;
            a1 += s_emb[1][k] * wv;
        }
        a0 = warp_sum(a0); a1 = warp_sum(a1);
        if (lane == 0){
            float bv = bxc[j];
            s_x[0][j] = a0 + bv; s_x[1][j] = a1 + bv;
            g_x[b0*En + j] = a0 + bv; g_x[(b0+1)*En + j] = a1 + bv;
        }
    }
    __syncthreads();

    // stage C: gates[j] ; 1024 j, warp per 32 j
    for (int j = wid; j < 1024; j += 32){
        const float* w1 = W_ih + j * En;
        const float* w2 = W_hh + j * Hn;
        float a0 = 0.f, a1 = 0.f;
        #pragma unroll
        for (int it = 0; it < 4; it++){
            int k = lane + it*32;
            float wv = w1[k];
            a0 += s_x[0][k] * wv; a1 += s_x[1][k] * wv;
        }
        #pragma unroll
        for (int it = 0; it < 8; it++){
            int k = lane + it*32;
            float wv = w2[k];
            a0 += s_h0[0][k] * wv; a1 += s_h0[1][k] * wv;
        }
        a0 = warp_sum(a0); a1 = warp_sum(a1);
        if (lane == 0){
            float bv = b_ih[j] + b_hh[j];
            s_gates[0][j] = a0 + bv; s_gates[1][j] = a1 + bv;
        }
    }
    __syncthreads();

    // stage D: lstm elementwise (512 threads -> 2x256)
    if (tid < 512){
        int bb = tid >> 8, h = tid & 255;
        int b = b0 + bb;
        float ig = sigmoidf_(s_gates[bb][h]);
        float fg = sigmoidf_(s_gates[bb][Hn + h]);
        float gg = tanhf(s_gates[bb][2*Hn + h]);
        float og = sigmoidf_(s_gates[bb][3*Hn + h]);
        float cs = fg * c0[b*Hn + h] + ig * gg;
        float hs = og * tanhf(cs);
        s_hs[bb][h] = hs; s_cs[bb][h] = cs;
        out[OFF_HS + b*Hn + h] = hs;
        out[OFF_CS + b*Hn + h] = cs;
    }
    __syncthreads();

    // stage E: dec[j] = [hs|cs] . Wdp_row(j) + bdp ; 512 j, warp per 16 j
    for (int j = wid; j < 512; j += 32){
        const float* wr = Wdp + j * 512;
        float a0 = 0.f, a1 = 0.f;
        #pragma unroll
        for (int it = 0; it < 8; it++){
            int k = lane + it*32;
            float wv = wr[k];
            a0 += s_hs[0][k] * wv; a1 += s_hs[1][k] * wv;
        }
        #pragma unroll
        for (int it = 0; it < 8; it++){
            int k = lane + it*32;
            float wv = wr[256 + k];
            a0 += s_cs[0][k] * wv; a1 += s_cs[1][k] * wv;
        }
        a0 = warp_sum(a0); a1 = warp_sum(a1);
        if (lane == 0){
            float bv = bdp[j];
            g_dec[b0*512 + j] = a0 + bv;
            g_dec[(b0+1)*512 + j] = a1 + bv;
        }
    }
}

// ============ K2: escore[b,t] = exp(Wv . tanh(ef+dec)) * mask ; 512 blocks ============
__global__ void __launch_bounds__(512) k_scores(const float* __restrict__ ef,
        const float* __restrict__ Wv, const float* __restrict__ mask){
    int b = blockIdx.x >> 3;
    int chunk = blockIdx.x & 7;
    int tid = threadIdx.x;
    int lane = tid & 31, wid = tid >> 5;   // 16 warps
    __shared__ float dec_s[512], wv_s[512];
    dec_s[tid] = g_dec[b*512 + tid];
    wv_s[tid]  = Wv[tid];
    __syncthreads();
    for (int tl = wid; tl < 50; tl += 16){
        int t = chunk * 50 + tl;
        const float4* efr = (const float4*)(ef + ((size_t)b * Tn + t) * 512);
        float acc = 0.0f;
        #pragma unroll
        for (int it = 0; it < 4; it++){
            int n4 = lane + it*32;          // float4 index
            float4 e4 = efr[n4];
            int n = n4 * 4;
            acc += wv_s[n+0] * tanh_fast(e4.x + dec_s[n+0]);
            acc += wv_s[n+1] * tanh_fast(e4.y + dec_s[n+1]);
            acc += wv_s[n+2] * tanh_fast(e4.z + dec_s[n+2]);
            acc += wv_s[n+3] * tanh_fast(e4.w + dec_s[n+3]);
        }
        acc = warp_sum(acc);
        if (lane == 0) g_escore[b*Tn + t] = expf(acc) * mask[b*Tn + t];
    }
}

// ============ K3: attn + partial c_t (atomics) ; 512 blocks (b, chunk) ============
__global__ void __launch_bounds__(512) k_attnct(const float* __restrict__ eo,
        const float* __restrict__ mask, const float* __restrict__ stmt,
        float* __restrict__ out){
    int b = blockIdx.x >> 3;
    int chunk = blockIdx.x & 7;
    int tid = threadIdx.x;
    __shared__ float red[512];
    __shared__ float attn_s[50];
    float e = (tid < Tn) ? g_escore[b*Tn + tid] : 0.0f;
    red[tid] = e; __syncthreads();
    #pragma unroll
    for (int k = 256; k > 0; k >>= 1){ if (tid < k) red[tid] += red[tid+k]; __syncthreads(); }
    float S = red[0];
    if (tid < 50){
        int t = chunk * 50 + tid;
        float a = g_escore[b*Tn + t] / S + stmt[b*Tn + t] * mask[b*Tn + t];
        attn_s[tid] = a;
        out[OFF_ATTN + b*Tn + t] = a;
    }
    __syncthreads();
    float acc = 0.0f;
    const float* eor = eo + ((size_t)b * Tn + chunk * 50) * 512 + tid;
    #pragma unroll 10
    for (int tt = 0; tt < 50; tt++)
        acc += attn_s[tt] * eor[(size_t)tt * 512];
    atomicAdd(&out[OFF_CT + b*512 + tid], acc);
}

// ============ K4: outhid + p_gen (2 batches / block) ============
__global__ void __launch_bounds__(512) k_mid(const float* __restrict__ Wo1,
        const float* __restrict__ bo1, const float* __restrict__ Wpg,
        const float* __restrict__ bpg, const float* __restrict__ out_ro,
        float* __restrict__ out){
    __shared__ float s_hs[2][256], s_cs[2][256], s_ct[2][512], s_xx[2][128];
    int tid = threadIdx.x;
    int lane = tid & 31, wid = tid >> 5;  // 16 warps
    int b0 = blockIdx.x * 2;
    // disjoint staging
    s_ct[0][tid] = out_ro[OFF_CT + b0*512 + tid];
    s_ct[1][tid] = out_ro[OFF_CT + (b0+1)*512 + tid];
    if (tid < 256){
        s_hs[0][tid] = out_ro[OFF_HS + b0*Hn + tid];
        s_cs[0][tid] = out_ro[OFF_CS + b0*Hn + tid];
    } else {
        int i = tid - 256;
        s_hs[1][i] = out_ro[OFF_HS + (b0+1)*Hn + i];
        s_cs[1][i] = out_ro[OFF_CS + (b0+1)*Hn + i];
    }
    if (tid < 128) s_xx[0][tid] = g_x[b0*En + tid];
    else if (tid < 256) s_xx[1][tid-128] = g_x[(b0+1)*En + (tid-128)];
    __syncthreads();

    // outhid: 256 j, warp per 16 j, K=768 = [hs(256) | ct(512)]
    for (int j = wid; j < 256; j += 16){
        const float* wr = Wo1 + j * 768;
        float a0 = 0.f, a1 = 0.f;
        #pragma unroll
        for (int it = 0; it < 8; it++){
            int k = lane + it*32;
            float wv = wr[k];
            a0 += s_hs[0][k] * wv; a1 += s_hs[1][k] * wv;
        }
        #pragma unroll
        for (int it = 0; it < 16; it++){
            int k = lane + it*32;
            float wv = wr[256 + k];
            a0 += s_ct[0][k] * wv; a1 += s_ct[1][k] * wv;
        }
        a0 = warp_sum(a0); a1 = warp_sum(a1);
        if (lane == 0){
            float bv = bo1[j];
            g_outhid[b0*Hn + j] = a0 + bv;
            g_outhid[(b0+1)*Hn + j] = a1 + bv;
        }
    }
    // p_gen: warps 0,1 (one per batch), K=1152 = [ct(512), hs(256), cs(256), x(128)]
    if (wid < 2){
        int bb = wid;
        float acc = 0.0f;
        for (int k = lane; k < 1152; k += 32){
            float v;
            if (k < 512)       v = s_ct[bb][k];
            else if (k < 768)  v = s_hs[bb][k - 512];
            else if (k < 1024) v = s_cs[bb][k - 768];
            else               v = s_xx[bb][k - 1024];
            acc += v * Wpg[k];
        }
        acc = warp_sum(acc);
        if (lane == 0) out[OFF_PGEN + b0 + bb] = sigmoidf_(acc + bpg[0]);
    }
}

// ============ K5: elog = exp(outhid @ Wo2^T + bo2), atomic row sums ============
__global__ void __launch_bounds__(256) k_logits(const float* __restrict__ W,
                                                const float* __restrict__ bias){
    __shared__ unsigned long long As2[32][65];
    __shared__ float Bs[32][264];
    int tid = threadIdx.x;
    int vbase = blockIdx.x * 256;
    int tx = tid & 31, ty = tid >> 5;
    int m0 = ty * 8, n0 = tx * 8;
    unsigned long long acc[8][4];
    #pragma unroll
    for (int i = 0; i < 8; i++){
        #pragma unroll
        for (int q = 0; q < 4; q++) acc[i][q] = 0ull;
    }
    for (int kc = 0; kc < Hn; kc += 32){
        #pragma unroll
        for (int i = tid; i < 2048; i += 256){
            int m = i >> 5, kk = i & 31;
            float a = g_outhid[m*Hn + kc + kk];
            As2[kk][m] = pack2(a, a);
        }
        #pragma unroll
        for (int i4 = tid; i4 < 2048; i4 += 256){
            int row = i4 >> 3, k4 = i4 & 7;
            int v = vbase + row;
            float4 wv = (v < Vn) ? *(const float4*)&W[(size_t)v*Hn + kc + k4*4]
                                 : make_float4(0.f,0.f,0.f,0.f);
            Bs[k4*4+0][row] = wv.x; Bs[k4*4+1][row] = wv.y;
            Bs[k4*4+2][row] = wv.z; Bs[k4*4+3][row] = wv.w;
        }
        __syncthreads();
        #pragma unroll
        for (int kk = 0; kk < 32; kk++){
            ulonglong2 p0 = *(const ulonglong2*)&Bs[kk][n0];
            ulonglong2 p1 = *(const ulonglong2*)&Bs[kk][n0+4];
            #pragma unroll
            for (int i = 0; i < 8; i++){
                unsigned long long a2 = As2[kk][m0 + i];
                acc[i][0] = fma2_(a2, p0.x, acc[i][0]);
                acc[i][1] = fma2_(a2, p0.y, acc[i][1]);
                acc[i][2] = fma2_(a2, p1.x, acc[i][2]);
                acc[i][3] = fma2_(a2, p1.y, acc[i][3]);
            }
        }
        __syncthreads();
    }
    float bvals[8];
    #pragma unroll
    for (int j = 0; j < 8; j++){
        int v = vbase + n0 + j;
        bvals[j] = (v < Vn) ? bias[v] : 0.0f;
    }
    #pragma unroll
    for (int i = 0; i < 8; i++){
        int m = m0 + i;
        float vals[8];
        unpack2(acc[i][0], vals[0], vals[1]);
        unpack2(acc[i][1], vals[2], vals[3]);
        unpack2(acc[i][2], vals[4], vals[5]);
        unpack2(acc[i][3], vals[6], vals[7]);
        float psum = 0.0f;
        #pragma unroll
        for (int j = 0; j < 8; j++){
            int v = vbase + n0 + j;
            if (v < Vn){
                float ev = expf(vals[j] + bvals[j]);
                g_elog[(size_t)m*Vn + v] = ev;
                psum += ev;
            }
        }
        psum = warp_sum(psum);
        if (tx == 0) atomicAdd(&g_rowsum[m], psum);
    }
}

// ============ K6: final base (float4) + coverage copy (float4) ============
__global__ void k_final(const float* __restrict__ extraz, const float* __restrict__ coverage,
                        float* __restrict__ out){
    int i4 = blockIdx.x * blockDim.x + threadIdx.x;
    if (i4 < (Bn*Tn)/4)
        ((float4*)(out + OFF_COV))[i4] = ((const float4*)coverage)[i4];
    if (i4 >= (Bn*(Vn+Xn))/4) return;
    int i = i4 * 4;
    int b = i / (Vn+Xn);
    int v = i - b*(Vn+Xn);
    float4 r;
    if (v < Vn){
        float pg = out[OFF_PGEN + b];
        float inv = pg / g_rowsum[b];
        const float4 e4 = *(const float4*)&g_elog[(size_t)b*Vn + v];
        r.x = e4.x * inv; r.y = e4.y * inv; r.z = e4.z * inv; r.w = e4.w * inv;
    } else {
        r = *(const float4*)&extraz[b*Xn + (v - Vn)];
    }
    *(float4*)&out[OFF_FINAL + i] = r;
}

// ============ K7: scatter ============
__global__ void k_scatter(const int* __restrict__ ebev, float* __restrict__ out){
    int i = blockIdx.x * blockDim.x + threadIdx.x;
    if (i >= Bn*Tn) return;
    int b = i / Tn;
    int ix = ebev[i];
    float pg = out[OFF_PGEN + b];
    float add = (1.0f - pg) * out[OFF_ATTN + i];
    atomicAdd(&out[OFF_FINAL + (size_t)b*(Vn+Xn) + ix], add);
}

extern "C" void kernel_launch(void* const* d_in, const int* in_sizes, int n_in,
                              void* d_out, int out_size){
    const int*   y_t_1    = (const int*)  d_in[0];
    const float* h0       = (const float*)d_in[1];
    const float* c0       = (const float*)d_in[2];
    const float* eo       = (const float*)d_in[3];
    const float* ef       = (const float*)d_in[4];
    const float* stmt     = (const float*)d_in[5];
    const float* mask     = (const float*)d_in[6];
    const float* c_t_1    = (const float*)d_in[7];
    const float* extraz   = (const float*)d_in[8];
    const int*   ebev     = (const int*)  d_in[9];
    const float* coverage = (const float*)d_in[10];
    const float* embedding = (const float*)d_in[n_in-16];
    const float* Wxc  = (const float*)d_in[n_in-15];
    const float* bxc  = (const float*)d_in[n_in-14];
    const float* W_ih = (const float*)d_in[n_in-13];
    const float* W_hh = (const float*)d_in[n_in-12];
    const float* b_ih = (const float*)d_in[n_in-11];
    const float* b_hh = (const float*)d_in[n_in-10];
    const float* Wdp  = (const float*)d_in[n_in-9];
    const float* bdp  = (const float*)d_in[n_in-8];
    const float* Wv   = (const float*)d_in[n_in-7];
    const float* Wpg  = (const float*)d_in[n_in-6];
    const float* bpg  = (const float*)d_in[n_in-5];
    const float* Wo1  = (const float*)d_in[n_in-4];
    const float* bo1  = (const float*)d_in[n_in-3];
    const float* Wo2  = (const float*)d_in[n_in-2];
    const float* bo2  = (const float*)d_in[n_in-1];
    float* out = (float*)d_out;

    k_pre<<<32, 1024>>>(y_t_1, c_t_1, embedding, Wxc, bxc, h0, c0,
                        W_ih, W_hh, b_ih, b_hh, Wdp, bdp, out);
    k_scores<<<512, 512>>>(ef, Wv, mask);
    k_attnct<<<512, 512>>>(eo, mask, stmt, out);
    k_mid<<<32, 512>>>(Wo1, bo1, Wpg, bpg, out, out);
    k_logits<<<(Vn + 255)/256, 256>>>(Wo2, bo2);
    k_final<<<(Bn*(Vn+Xn)/4 + 255)/256, 256>>>(extraz, coverage, out);
    k_scatter<<<(Bn*Tn + 255)/256, 256>>>(ebev, out);
}